// round 10
// baseline (speedup 1.0000x reference)
#include <cuda_runtime.h>
#include <cuda_fp16.h>
#include <cstdint>

// Shapes fixed by the reference
#define N_NODES  100000
#define IN_DIM   128
#define KDIM     256          // 2*IN_DIM
#define HID      64
#define WARPS    7            // warps per block (one block per SM)
#define NTHREADS (WARPS*32)
#define CHUNK_E  48           // edges per warp chunk (M=48, 3 m-tiles)
#define MTILES   3
#define LDAS     132          // As row stride in 32-bit words (128 data + 4 pad)
#define LDW      132          // W1t row stride in 32-bit words (128 data + 4 pad)
#define GRID     152          // 1 block per SM

#define SMEM_BYTES ((WARPS*CHUNK_E*LDAS + HID*LDW)*4 + (64+64+1)*4)

// fp16 copy of z, gathered via cp.async (25.6 MB static scratch)
__device__ __half zh_g[N_NODES * IN_DIM];

__global__ void convert_z_kernel(const float* __restrict__ z, int n) {
    const int stride = gridDim.x * blockDim.x;
    const int n4 = n >> 2;
    const float4* z4 = reinterpret_cast<const float4*>(z);
    __half2* o2 = reinterpret_cast<__half2*>(zh_g);
    for (int i = blockIdx.x * blockDim.x + threadIdx.x; i < n4; i += stride) {
        float4 v = z4[i];
        o2[i * 2 + 0] = __floats2half2_rn(v.x, v.y);
        o2[i * 2 + 1] = __floats2half2_rn(v.z, v.w);
    }
}

__device__ __forceinline__ void mma_fp16(float* c, const uint32_t* a,
                                         uint32_t b0, uint32_t b1) {
    asm volatile(
        "mma.sync.aligned.m16n8k16.row.col.f32.f16.f16.f32 "
        "{%0,%1,%2,%3}, {%4,%5,%6,%7}, {%8,%9}, {%0,%1,%2,%3};"
        : "+f"(c[0]), "+f"(c[1]), "+f"(c[2]), "+f"(c[3])
        : "r"(a[0]), "r"(a[1]), "r"(a[2]), "r"(a[3]), "r"(b0), "r"(b1));
}

struct GatherCtx {
    const int* e32;
    const long long* e64;
    bool is64;
    const char* zb;
    uint32_t* As32;           // this warp's 48-row slab
    int NE, lane, halfSel, sub;
};

// Issue cp.async gather of one 48-edge chunk into this warp's slab (no waits).
__device__ __forceinline__ void issue_gather(const GatherCtx& c, int chunk) {
    const int base = chunk * CHUNK_E;
    // Indices for edges 0..31 (lane) and 32..47 (lane<16)
    long long sIdx0 = 0, dIdx0 = 0, sIdx1 = 0, dIdx1 = 0;
    {
        const int ge = base + c.lane;
        if (ge < c.NE) {
            if (c.is64) { sIdx0 = c.e64[ge]; dIdx0 = c.e64[(long long)c.NE + ge]; }
            else        { sIdx0 = (long long)c.e32[ge]; dIdx0 = (long long)c.e32[c.NE + ge]; }
        }
    }
    if (c.lane < 16) {
        const int ge = base + 32 + c.lane;
        if (ge < c.NE) {
            if (c.is64) { sIdx1 = c.e64[ge]; dIdx1 = c.e64[(long long)c.NE + ge]; }
            else        { sIdx1 = (long long)c.e32[ge]; dIdx1 = (long long)c.e32[c.NE + ge]; }
        }
    }
    #pragma unroll 8
    for (int i = 0; i < CHUNK_E; i++) {
        const long long s = (i < 32) ? __shfl_sync(0xffffffffu, sIdx0, i)
                                     : __shfl_sync(0xffffffffu, sIdx1, i - 32);
        const long long d = (i < 32) ? __shfl_sync(0xffffffffu, dIdx0, i)
                                     : __shfl_sync(0xffffffffu, dIdx1, i - 32);
        const long long row = c.halfSel ? d : s;
        const char* src = c.zb + (row << 8) + c.sub * 16;
        char* dstp = reinterpret_cast<char*>(c.As32)
                   + i * (LDAS * 4) + c.halfSel * 256 + c.sub * 16;
        const uint32_t daddr = (uint32_t)__cvta_generic_to_shared(dstp);
        asm volatile("cp.async.cg.shared.global [%0], [%1], 16;\n"
                     :: "r"(daddr), "l"(src));
    }
    asm volatile("cp.async.commit_group;\n");
}

__global__ __launch_bounds__(NTHREADS, 1)
void mask_predictor_kernel(const void* __restrict__ eidx_raw,
                           const float* __restrict__ W1,
                           const float* __restrict__ b1,
                           const float* __restrict__ W2,
                           const float* __restrict__ b2,
                           float* __restrict__ out,
                           int NE) {
    extern __shared__ unsigned char smem_raw[];
    uint32_t* As32  = reinterpret_cast<uint32_t*>(smem_raw);     // [336][132] words (fp16x2)
    uint32_t* W1t32 = As32 + WARPS * CHUNK_E * LDAS;             // [64][132] words (W1^T)
    float*    b1s   = reinterpret_cast<float*>(W1t32 + HID * LDW);
    float*    w2s   = b1s + 64;
    float*    b2s   = w2s + 64;
    __half*   W1th  = reinterpret_cast<__half*>(W1t32);          // halves, row stride 264

    const int tid  = threadIdx.x;
    const int warp = tid >> 5;
    const int lane = tid & 31;
    const int g    = lane >> 2;   // groupID (0..7)
    const int m    = lane & 3;    // thread-in-group (0..3)

    // ---- Detect edge_index dtype (int64 vs int32) uniformly ----
    const int*       e32 = reinterpret_cast<const int*>(eidx_raw);
    const long long* e64 = reinterpret_cast<const long long*>(eidx_raw);
    bool is64 = true;
    #pragma unroll
    for (int i = 1; i < 32; i += 2) if (e32[i] != 0) is64 = false;

    // ---- Stage W1^T (fp16), b1, W2, b2 (read-only after this barrier) ----
    for (int i = tid; i < KDIM * HID; i += NTHREADS) {
        const int k = i >> 6, n = i & 63;
        W1th[n * (LDW * 2) + k] = __float2half(W1[i]);
    }
    if (tid < 64) { b1s[tid] = b1[tid]; w2s[tid] = W2[tid]; }
    if (tid == 64) { b2s[0] = b2[0]; }
    __syncthreads();

    uint32_t* myAs = As32 + warp * CHUNK_E * LDAS;  // this warp's private slab

    GatherCtx ctx;
    ctx.e32 = e32; ctx.e64 = e64; ctx.is64 = is64;
    ctx.zb = reinterpret_cast<const char*>(zh_g);
    ctx.As32 = myAs; ctx.NE = NE;
    ctx.lane = lane;
    ctx.halfSel = lane >> 4;
    ctx.sub = lane & 15;

    // Each warp is an independent pipeline over its own 48-row slab; work is
    // global-warp-strided 48-edge chunks. No block barriers in the loop.
    const int nChunks = (NE + CHUNK_E - 1) / CHUNK_E;
    const int wStride = GRID * WARPS;

    int chunk = blockIdx.x * WARPS + warp;
    if (chunk < nChunks) issue_gather(ctx, chunk);

    for (; chunk < nChunks; chunk += wStride) {
        asm volatile("cp.async.wait_group 0;\n" ::: "memory");
        __syncwarp();   // make lane-written As rows visible warp-wide

        // ---- GEMM: warp computes 48 edges x 64 cols, fp16 m16n8k16, fp32 acc ----
        float acc[MTILES][8][4];
        #pragma unroll
        for (int mt = 0; mt < MTILES; mt++)
            #pragma unroll
            for (int nt = 0; nt < 8; nt++)
                #pragma unroll
                for (int r = 0; r < 4; r++) acc[mt][nt][r] = 0.f;

        #pragma unroll 2
        for (int kt = 0; kt < 16; kt++) {
            const int kw = kt * 8 + m;
            uint32_t a[MTILES][4];
            #pragma unroll
            for (int mt = 0; mt < MTILES; mt++) {
                const int base = (mt * 16 + g) * LDAS;
                a[mt][0] = myAs[base + kw];
                a[mt][1] = myAs[base + 8 * LDAS + kw];
                a[mt][2] = myAs[base + kw + 4];
                a[mt][3] = myAs[base + 8 * LDAS + kw + 4];
            }
            #pragma unroll
            for (int nt = 0; nt < 8; nt++) {
                const uint32_t b0  = W1t32[(nt * 8 + g) * LDW + kw];
                const uint32_t b1v = W1t32[(nt * 8 + g) * LDW + kw + 4];
                mma_fp16(acc[0][nt], a[0], b0, b1v);
                mma_fp16(acc[1][nt], a[1], b0, b1v);
                mma_fp16(acc[2][nt], a[2], b0, b1v);
            }
        }

        __syncwarp();   // all lanes done reading As before overwrite

        // ---- Prefetch next chunk's gather; lands during epilogue + peers ----
        const int nxt = chunk + wStride;
        if (nxt < nChunks) issue_gather(ctx, nxt);

        // ---- Epilogue: bias + ReLU + W2 dot + sigmoid ----
        float p[2 * MTILES];  // rows mt*16 + {g, g+8}
        #pragma unroll
        for (int j = 0; j < 2 * MTILES; j++) p[j] = 0.f;
        #pragma unroll
        for (int mt = 0; mt < MTILES; mt++) {
            #pragma unroll
            for (int nt = 0; nt < 8; nt++) {
                const int c = nt * 8 + 2 * m;
                const float ba = b1s[c], bb = b1s[c + 1];
                const float wa = w2s[c], wb = w2s[c + 1];
                float h;
                h = acc[mt][nt][0] + ba; p[mt * 2 + 0] += fmaxf(h, 0.f) * wa;
                h = acc[mt][nt][1] + bb; p[mt * 2 + 0] += fmaxf(h, 0.f) * wb;
                h = acc[mt][nt][2] + ba; p[mt * 2 + 1] += fmaxf(h, 0.f) * wa;
                h = acc[mt][nt][3] + bb; p[mt * 2 + 1] += fmaxf(h, 0.f) * wb;
            }
        }
        #pragma unroll
        for (int j = 0; j < 2 * MTILES; j++) {
            p[j] += __shfl_xor_sync(0xffffffffu, p[j], 1);
            p[j] += __shfl_xor_sync(0xffffffffu, p[j], 2);
        }
        if (m == 0) {
            const float bias2 = b2s[0];
            const int base = chunk * CHUNK_E;
            #pragma unroll
            for (int j = 0; j < 2 * MTILES; j++) {
                const int e = base + (j >> 1) * 16 + (j & 1) * 8 + g;
                if (e < NE)
                    out[e] = 1.f / (1.f + __expf(-(p[j] + bias2)));
            }
        }
    }
}

extern "C" void kernel_launch(void* const* d_in, const int* in_sizes, int n_in,
                              void* d_out, int out_size) {
    const float* z    = (const float*)d_in[0];
    const void*  eidx = d_in[1];
    const float* W1   = (const float*)d_in[2];
    const float* b1   = (const float*)d_in[3];
    const float* W2   = (const float*)d_in[4];
    const float* b2   = (const float*)d_in[5];
    float*       out  = (float*)d_out;

    const int NE = in_sizes[1] / 2;  // edge_index is (2, E)
    const int nZ = in_sizes[0];      // N_NODES * IN_DIM

    static bool attr_set = false;
    if (!attr_set) {
        cudaFuncSetAttribute(mask_predictor_kernel,
                             cudaFuncAttributeMaxDynamicSharedMemorySize, SMEM_BYTES);
        attr_set = true;
    }

    convert_z_kernel<<<152, 256>>>(z, nZ);
    mask_predictor_kernel<<<GRID, NTHREADS, SMEM_BYTES>>>(eidx, W1, b1, W2, b2, out, NE);
}

// round 12
// speedup vs baseline: 1.3502x; 1.3502x over previous
#include <cuda_runtime.h>
#include <cuda_fp16.h>
#include <cstdint>

// Shapes fixed by the reference
#define N_NODES  100000
#define IN_DIM   128
#define KDIM     256          // 2*IN_DIM
#define HID      64
#define WARPS    8            // warps per block (one block per SM)
#define NTHREADS (WARPS*32)
#define CHUNK_E  32           // edges per warp chunk (M=32)
#define LDAS     132          // As row stride in 32-bit words (128 data + 4 pad)
#define LDW      132          // W1t row stride in 32-bit words (128 data + 4 pad)
#define GRID     152          // 1 block per SM

#define SMEM_BYTES ((WARPS*CHUNK_E*LDAS + HID*LDW)*4 + (64+64+1)*4)

// fp16 copy of z, gathered via cp.async (25.6 MB static scratch)
__device__ __half zh_g[N_NODES * IN_DIM];

__global__ void convert_z_kernel(const float* __restrict__ z, int n) {
    const int stride = gridDim.x * blockDim.x;
    const int n4 = n >> 2;
    const float4* z4 = reinterpret_cast<const float4*>(z);
    __half2* o2 = reinterpret_cast<__half2*>(zh_g);
    for (int i = blockIdx.x * blockDim.x + threadIdx.x; i < n4; i += stride) {
        float4 v = z4[i];
        o2[i * 2 + 0] = __floats2half2_rn(v.x, v.y);
        o2[i * 2 + 1] = __floats2half2_rn(v.z, v.w);
    }
}

__device__ __forceinline__ void mma_fp16(float* c, const uint32_t* a,
                                         uint32_t b0, uint32_t b1) {
    asm volatile(
        "mma.sync.aligned.m16n8k16.row.col.f32.f16.f16.f32 "
        "{%0,%1,%2,%3}, {%4,%5,%6,%7}, {%8,%9}, {%0,%1,%2,%3};"
        : "+f"(c[0]), "+f"(c[1]), "+f"(c[2]), "+f"(c[3])
        : "r"(a[0]), "r"(a[1]), "r"(a[2]), "r"(a[3]), "r"(b0), "r"(b1));
}

struct GatherCtx {
    const int* e32;
    const long long* e64;
    bool is64;
    const char* zb;
    uint32_t* As32;           // this warp's 32-row slab
    int NE, lane, halfSel, sub;
};

// Issue cp.async gather of one 32-edge chunk into this warp's slab (no waits).
__device__ __forceinline__ void issue_gather(const GatherCtx& c, int chunk) {
    const int ge = chunk * CHUNK_E + c.lane;
    long long sIdx = 0, dIdx = 0;
    if (ge < c.NE) {
        if (c.is64) { sIdx = c.e64[ge]; dIdx = c.e64[(long long)c.NE + ge]; }
        else        { sIdx = (long long)c.e32[ge]; dIdx = (long long)c.e32[c.NE + ge]; }
    }
    #pragma unroll 8
    for (int i = 0; i < 32; i++) {
        const long long s = __shfl_sync(0xffffffffu, sIdx, i);
        const long long d = __shfl_sync(0xffffffffu, dIdx, i);
        const long long row = c.halfSel ? d : s;
        const char* src = c.zb + (row << 8) + c.sub * 16;
        char* dstp = reinterpret_cast<char*>(c.As32)
                   + i * (LDAS * 4) + c.halfSel * 256 + c.sub * 16;
        const uint32_t daddr = (uint32_t)__cvta_generic_to_shared(dstp);
        asm volatile("cp.async.cg.shared.global [%0], [%1], 16;\n"
                     :: "r"(daddr), "l"(src));
    }
    asm volatile("cp.async.commit_group;\n");
}

__global__ __launch_bounds__(NTHREADS, 1)
void mask_predictor_kernel(const void* __restrict__ eidx_raw,
                           const float* __restrict__ W1,
                           const float* __restrict__ b1,
                           const float* __restrict__ W2,
                           const float* __restrict__ b2,
                           float* __restrict__ out,
                           int NE) {
    extern __shared__ unsigned char smem_raw[];
    uint32_t* As32  = reinterpret_cast<uint32_t*>(smem_raw);     // [256][132] words (fp16x2)
    uint32_t* W1t32 = As32 + WARPS * CHUNK_E * LDAS;             // [64][132] words (W1^T)
    float*    b1s   = reinterpret_cast<float*>(W1t32 + HID * LDW);
    float*    w2s   = b1s + 64;
    float*    b2s   = w2s + 64;
    __half*   W1th  = reinterpret_cast<__half*>(W1t32);          // halves, row stride 264

    const int tid  = threadIdx.x;
    const int warp = tid >> 5;
    const int lane = tid & 31;
    const int g    = lane >> 2;   // groupID (0..7)
    const int m    = lane & 3;    // thread-in-group (0..3)

    // ---- Detect edge_index dtype (int64 vs int32) uniformly ----
    const int*       e32 = reinterpret_cast<const int*>(eidx_raw);
    const long long* e64 = reinterpret_cast<const long long*>(eidx_raw);
    bool is64 = true;
    #pragma unroll
    for (int i = 1; i < 32; i += 2) if (e32[i] != 0) is64 = false;

    // ---- Stage W1^T (fp16), b1, W2, b2 (read-only after this barrier) ----
    for (int i = tid; i < KDIM * HID; i += NTHREADS) {
        const int k = i >> 6, n = i & 63;
        W1th[n * (LDW * 2) + k] = __float2half(W1[i]);
    }
    if (tid < 64) { b1s[tid] = b1[tid]; w2s[tid] = W2[tid]; }
    if (tid == 64) { b2s[0] = b2[0]; }
    __syncthreads();

    // ---- Cache B fragments for kt=0..7 in registers (loop-invariant!) ----
    // Halves per-chunk B smem traffic and un-gates HMMA from the LDS queue
    // for the first half of every mainloop.
    uint32_t bc[8][8][2];
    #pragma unroll
    for (int kt = 0; kt < 8; kt++) {
        const int kw = kt * 8 + m;
        #pragma unroll
        for (int nt = 0; nt < 8; nt++) {
            bc[kt][nt][0] = W1t32[(nt * 8 + g) * LDW + kw];
            bc[kt][nt][1] = W1t32[(nt * 8 + g) * LDW + kw + 4];
        }
    }

    uint32_t* myAs = As32 + warp * CHUNK_E * LDAS;  // this warp's private slab

    GatherCtx ctx;
    ctx.e32 = e32; ctx.e64 = e64; ctx.is64 = is64;
    ctx.zb = reinterpret_cast<const char*>(zh_g);
    ctx.As32 = myAs; ctx.NE = NE;
    ctx.lane = lane;
    ctx.halfSel = lane >> 4;
    ctx.sub = lane & 15;

    // Each warp is an independent pipeline over its own 32-row slab; work is
    // global-warp-strided 32-edge chunks. No block barriers in the loop.
    const int nChunks = (NE + CHUNK_E - 1) / CHUNK_E;
    const int wStride = GRID * WARPS;

    int chunk = blockIdx.x * WARPS + warp;
    if (chunk < nChunks) issue_gather(ctx, chunk);

    for (; chunk < nChunks; chunk += wStride) {
        asm volatile("cp.async.wait_group 0;\n" ::: "memory");
        __syncwarp();   // make lane-written As rows visible warp-wide

        // ---- GEMM: warp computes 32 edges x 64 cols, fp16 m16n8k16, fp32 acc ----
        float acc[2][8][4];
        #pragma unroll
        for (int mt = 0; mt < 2; mt++)
            #pragma unroll
            for (int nt = 0; nt < 8; nt++)
                #pragma unroll
                for (int r = 0; r < 4; r++) acc[mt][nt][r] = 0.f;

        // kt 0..7: B from registers (only A LDS in flight)
        #pragma unroll
        for (int kt = 0; kt < 8; kt++) {
            const int kw = kt * 8 + m;
            uint32_t a[2][4];
            #pragma unroll
            for (int mt = 0; mt < 2; mt++) {
                const int base = (mt * 16 + g) * LDAS;
                a[mt][0] = myAs[base + kw];
                a[mt][1] = myAs[base + 8 * LDAS + kw];
                a[mt][2] = myAs[base + kw + 4];
                a[mt][3] = myAs[base + 8 * LDAS + kw + 4];
            }
            #pragma unroll
            for (int nt = 0; nt < 8; nt++) {
                mma_fp16(acc[0][nt], a[0], bc[kt][nt][0], bc[kt][nt][1]);
                mma_fp16(acc[1][nt], a[1], bc[kt][nt][0], bc[kt][nt][1]);
            }
        }

        // kt 8..15: B from smem
        #pragma unroll
        for (int kt = 8; kt < 16; kt++) {
            const int kw = kt * 8 + m;
            uint32_t a[2][4];
            #pragma unroll
            for (int mt = 0; mt < 2; mt++) {
                const int base = (mt * 16 + g) * LDAS;
                a[mt][0] = myAs[base + kw];
                a[mt][1] = myAs[base + 8 * LDAS + kw];
                a[mt][2] = myAs[base + kw + 4];
                a[mt][3] = myAs[base + 8 * LDAS + kw + 4];
            }
            #pragma unroll
            for (int nt = 0; nt < 8; nt++) {
                const uint32_t b0  = W1t32[(nt * 8 + g) * LDW + kw];
                const uint32_t b1v = W1t32[(nt * 8 + g) * LDW + kw + 4];
                mma_fp16(acc[0][nt], a[0], b0, b1v);
                mma_fp16(acc[1][nt], a[1], b0, b1v);
            }
        }

        __syncwarp();   // all lanes done reading As before overwrite

        // ---- Prefetch next chunk's gather; lands during epilogue + peers ----
        const int nxt = chunk + wStride;
        if (nxt < nChunks) issue_gather(ctx, nxt);

        // ---- Epilogue: bias + ReLU + W2 dot + sigmoid ----
        float p[4] = {0.f, 0.f, 0.f, 0.f};  // rows g, g+8, g+16, g+24
        #pragma unroll
        for (int mt = 0; mt < 2; mt++) {
            #pragma unroll
            for (int nt = 0; nt < 8; nt++) {
                const int c = nt * 8 + 2 * m;
                const float ba = b1s[c], bb = b1s[c + 1];
                const float wa = w2s[c], wb = w2s[c + 1];
                float h;
                h = acc[mt][nt][0] + ba; p[mt * 2 + 0] += fmaxf(h, 0.f) * wa;
                h = acc[mt][nt][1] + bb; p[mt * 2 + 0] += fmaxf(h, 0.f) * wb;
                h = acc[mt][nt][2] + ba; p[mt * 2 + 1] += fmaxf(h, 0.f) * wa;
                h = acc[mt][nt][3] + bb; p[mt * 2 + 1] += fmaxf(h, 0.f) * wb;
            }
        }
        #pragma unroll
        for (int j = 0; j < 4; j++) {
            p[j] += __shfl_xor_sync(0xffffffffu, p[j], 1);
            p[j] += __shfl_xor_sync(0xffffffffu, p[j], 2);
        }
        if (m == 0) {
            const float bias2 = b2s[0];
            const int base = chunk * CHUNK_E;
            #pragma unroll
            for (int j = 0; j < 4; j++) {
                const int e = base + (j >> 1) * 16 + (j & 1) * 8 + g;
                if (e < NE)
                    out[e] = 1.f / (1.f + __expf(-(p[j] + bias2)));
            }
        }
    }
}

extern "C" void kernel_launch(void* const* d_in, const int* in_sizes, int n_in,
                              void* d_out, int out_size) {
    const float* z    = (const float*)d_in[0];
    const void*  eidx = d_in[1];
    const float* W1   = (const float*)d_in[2];
    const float* b1   = (const float*)d_in[3];
    const float* W2   = (const float*)d_in[4];
    const float* b2   = (const float*)d_in[5];
    float*       out  = (float*)d_out;

    const int NE = in_sizes[1] / 2;  // edge_index is (2, E)
    const int nZ = in_sizes[0];      // N_NODES * IN_DIM

    static bool attr_set = false;
    if (!attr_set) {
        cudaFuncSetAttribute(mask_predictor_kernel,
                             cudaFuncAttributeMaxDynamicSharedMemorySize, SMEM_BYTES);
        attr_set = true;
    }

    convert_z_kernel<<<152, 256>>>(z, nZ);
    mask_predictor_kernel<<<GRID, NTHREADS, SMEM_BYTES>>>(eidx, W1, b1, W2, b2, out, NE);
}